// round 3
// baseline (speedup 1.0000x reference)
#include <cuda_runtime.h>
#include <cuda_bf16.h>
#include <cstdint>

// ============================================================================
// Problem constants
// ============================================================================
#define T_TOK   8192          // B*S tokens
#define HDIM    2048
#define NEXP    8
#define NSLOTS  17408         // 2*T + 8*128 padding
#define MAX_TILES 136         // sum ceil(count_e/128) <= 2T/128 + E
#define KSTEPS  64            // K=2048 / 32 per k-step

// ============================================================================
// PTX helpers — ONLY family-portable (non-"a") instructions:
// mma.sync (sm_80), ldmatrix (sm_75), cp.async (sm_80).
// ============================================================================
__device__ __forceinline__ uint32_t smem_to_u32(const void* p) {
    uint32_t a;
    asm("{ .reg .u64 t; cvta.to.shared.u64 t, %1; cvt.u32.u64 %0, t; }"
        : "=r"(a) : "l"(p));
    return a;
}

#define CP_ASYNC16(smem, gmem) \
    asm volatile("cp.async.cg.shared.global [%0], [%1], 16;" \
        :: "r"(smem), "l"(gmem))
#define CP_COMMIT() asm volatile("cp.async.commit_group;" ::: "memory")
#define CP_WAIT2()  asm volatile("cp.async.wait_group 2;" ::: "memory")

__device__ __forceinline__ void ldsm_x4(uint32_t* r, uint32_t addr) {
    asm volatile("ldmatrix.sync.aligned.m8n8.x4.shared.b16 {%0,%1,%2,%3}, [%4];"
        : "=r"(r[0]), "=r"(r[1]), "=r"(r[2]), "=r"(r[3]) : "r"(addr));
}

__device__ __forceinline__ void mma16816(float* d, const uint32_t* a,
                                         const uint32_t* b) {
    asm volatile(
        "mma.sync.aligned.m16n8k16.row.col.f32.bf16.bf16.f32 "
        "{%0,%1,%2,%3}, {%4,%5,%6,%7}, {%8,%9}, {%0,%1,%2,%3};"
        : "+f"(d[0]), "+f"(d[1]), "+f"(d[2]), "+f"(d[3])
        : "r"(a[0]), "r"(a[1]), "r"(a[2]), "r"(a[3]), "r"(b[0]), "r"(b[1]));
}

// pack (a,b) -> bf16x2 with a in low half (memory order [a, b])
#define CVT_BF16X2_F32(result, a, b) \
    asm("cvt.rn.satfinite.bf16x2.f32 %0, %1, %2;" : "=r"(result) : "f"(b), "f"(a))

// ============================================================================
// Device scratch (no allocations allowed — static __device__ arrays)
// ============================================================================
__device__ int   g_count[NEXP];
__device__ int   g_cursor[NEXP];
__device__ int   g_base[NEXP];
__device__ int   g_tile_expert[MAX_TILES];
__device__ int   g_tile_mbase[MAX_TILES];
__device__ int   g_num_tiles;
__device__ int   g_topi[T_TOK * 2];
__device__ float g_topw[T_TOK * 2];
__device__ int   g_slot_token[NSLOTS];
__device__ float g_slot_w[NSLOTS];
__device__ int   g_tok_slot[T_TOK * 2];

__device__ __nv_bfloat16 g_xh[(size_t)NSLOTS * HDIM];          // 68 MB
__device__ __nv_bfloat16 g_xl[(size_t)NSLOTS * HDIM];          // 68 MB
__device__ __nv_bfloat16 g_wh[(size_t)NEXP * HDIM * HDIM];     // 64 MB
__device__ __nv_bfloat16 g_wl[(size_t)NEXP * HDIM * HDIM];     // 64 MB
__device__ float g_ybuf[(size_t)NSLOTS * HDIM];                // 143 MB

// ============================================================================
// K0: reset scratch state (graph is replayed — must reinit every launch)
// ============================================================================
__global__ void moe_init_kernel() {
    int tid = threadIdx.x;
    if (tid < NEXP) { g_count[tid] = 0; g_cursor[tid] = 0; }
    for (int i = tid; i < NSLOTS; i += blockDim.x) g_slot_token[i] = -1;
}

// ============================================================================
// K1: router — logits (to output tail) + top-2 normalized weights.
// One warp per token.
// ============================================================================
__global__ void moe_router_kernel(const float* __restrict__ x,
                                  const float* __restrict__ gw,
                                  float* __restrict__ logits_out) {
    int warp = (blockIdx.x * blockDim.x + threadIdx.x) >> 5;
    int lane = threadIdx.x & 31;
    if (warp >= T_TOK) return;
    const float4* xr = (const float4*)(x + (size_t)warp * HDIM);
    float acc[NEXP];
#pragma unroll
    for (int e = 0; e < NEXP; e++) acc[e] = 0.f;
    for (int i = lane; i < HDIM / 4; i += 32) {
        float4 xv = xr[i];
#pragma unroll
        for (int e = 0; e < NEXP; e++) {
            float4 gv = ((const float4*)(gw + e * HDIM))[i];
            acc[e] += xv.x * gv.x + xv.y * gv.y + xv.z * gv.z + xv.w * gv.w;
        }
    }
#pragma unroll
    for (int e = 0; e < NEXP; e++)
#pragma unroll
        for (int off = 16; off; off >>= 1)
            acc[e] += __shfl_xor_sync(0xFFFFFFFFu, acc[e], off);
    if (lane == 0) {
#pragma unroll
        for (int e = 0; e < NEXP; e++) logits_out[warp * NEXP + e] = acc[e];
        int i1 = 0; float l1 = acc[0];
#pragma unroll
        for (int e = 1; e < NEXP; e++) if (acc[e] > l1) { l1 = acc[e]; i1 = e; }
        int i2 = -1; float l2 = -3.4e38f;
#pragma unroll
        for (int e = 0; e < NEXP; e++)
            if (e != i1 && acc[e] > l2) { l2 = acc[e]; i2 = e; }
        float ex = expf(l2 - l1);
        float w1 = 1.0f / (1.0f + ex);
        float w2 = ex / (1.0f + ex);
        g_topi[warp * 2 + 0] = i1;  g_topw[warp * 2 + 0] = w1;
        g_topi[warp * 2 + 1] = i2;  g_topw[warp * 2 + 1] = w2;
        atomicAdd(&g_count[i1], 1);
        atomicAdd(&g_count[i2], 1);
    }
}

// ============================================================================
// K2: serial scan — padded slot bases + tile map
// ============================================================================
__global__ void moe_scan_kernel() {
    if (threadIdx.x == 0 && blockIdx.x == 0) {
        int run = 0, nt = 0;
        for (int e = 0; e < NEXP; e++) {
            g_base[e] = run;
            int c = g_count[e];
            int tiles = (c + 127) >> 7;
            for (int t = 0; t < tiles; t++) {
                g_tile_expert[nt] = e;
                g_tile_mbase[nt]  = run + t * 128;
                nt++;
            }
            run += tiles << 7;
        }
        g_num_tiles = nt;
    }
}

// ============================================================================
// K3: scatter tokens into per-expert slot lists
// ============================================================================
__global__ void moe_assign_kernel() {
    int t = blockIdx.x * blockDim.x + threadIdx.x;
    if (t >= T_TOK) return;
#pragma unroll
    for (int k = 0; k < 2; k++) {
        int e = g_topi[t * 2 + k];
        int pos = atomicAdd(&g_cursor[e], 1);
        int slot = g_base[e] + pos;
        g_slot_token[slot] = t;
        g_slot_w[slot] = g_topw[t * 2 + k];
        g_tok_slot[t * 2 + k] = slot;
    }
}

// ============================================================================
// K4a: convert+permute x -> slot-ordered bf16 hi/lo
// ============================================================================
__global__ void moe_convert_x_kernel(const float* __restrict__ x) {
    int i = blockIdx.x * blockDim.x + threadIdx.x;      // NSLOTS*512
    int slot = i >> 9;
    int j = i & 511;                                    // float4 within row
    int tok = g_slot_token[slot];
    uint2 h = make_uint2(0u, 0u), l = make_uint2(0u, 0u);
    if (tok >= 0) {
        float4 v = *(const float4*)(x + (size_t)tok * HDIM + j * 4);
        uint32_t h01, h23, l01, l23;
        CVT_BF16X2_F32(h01, v.x, v.y);
        CVT_BF16X2_F32(h23, v.z, v.w);
        float r0 = v.x - __uint_as_float(h01 << 16);
        float r1 = v.y - __uint_as_float(h01 & 0xFFFF0000u);
        float r2 = v.z - __uint_as_float(h23 << 16);
        float r3 = v.w - __uint_as_float(h23 & 0xFFFF0000u);
        CVT_BF16X2_F32(l01, r0, r1);
        CVT_BF16X2_F32(l23, r2, r3);
        h = make_uint2(h01, h23);
        l = make_uint2(l01, l23);
    }
    size_t o = (size_t)slot * 512 + j;
    ((uint2*)g_xh)[o] = h;
    ((uint2*)g_xl)[o] = l;
}

// ============================================================================
// K4b: convert expert weights -> bf16 hi/lo
// ============================================================================
__global__ void moe_convert_w_kernel(const float* __restrict__ ew) {
    size_t i = (size_t)blockIdx.x * blockDim.x + threadIdx.x;  // 8*2048*2048/4
    float4 v = ((const float4*)ew)[i];
    uint32_t h01, h23, l01, l23;
    CVT_BF16X2_F32(h01, v.x, v.y);
    CVT_BF16X2_F32(h23, v.z, v.w);
    float r0 = v.x - __uint_as_float(h01 << 16);
    float r1 = v.y - __uint_as_float(h01 & 0xFFFF0000u);
    float r2 = v.z - __uint_as_float(h23 << 16);
    float r3 = v.w - __uint_as_float(h23 & 0xFFFF0000u);
    CVT_BF16X2_F32(l01, r0, r1);
    CVT_BF16X2_F32(l23, r2, r3);
    ((uint2*)g_wh)[i] = make_uint2(h01, h23);
    ((uint2*)g_wl)[i] = make_uint2(l01, l23);
}

// ============================================================================
// K5: grouped GEMM — 128(M)x128(N)x2048(K), mma.sync bf16 hi/lo (3 terms),
// 4-stage cp.async pipeline, padded 80B SMEM rows (ldmatrix conflict-free).
// ============================================================================
#define RS        40                      // padded row length in bf16 elems
#define MAT_B     (128 * RS * 2)          // 10240 B per matrix
#define STAGE_B   (4 * MAT_B)             // 40960 B per stage (Ah,Al,Bh,Bl)
#define NSTAGE    4
#define SMEM_DYN  (1024 + NSTAGE * STAGE_B)   // 164864 B

__global__ void __launch_bounds__(256, 1)
moe_gemm_kernel() {
    int tile = blockIdx.y;
    if (tile >= g_num_tiles) return;
    int n0    = blockIdx.x * 128;
    int e     = g_tile_expert[tile];
    int mbase = g_tile_mbase[tile];

    extern __shared__ char dsm[];
    float* s_w = (float*)dsm;                       // 128 floats
    uint32_t sb = smem_to_u32(dsm);
    uint32_t st0 = sb + 1024;

    int tid = threadIdx.x, lane = tid & 31, wid = tid >> 5;
    int wm = wid >> 2, wn = wid & 3;                // 2 x 4 warp grid

    if (tid < 128) s_w[tid] = g_slot_w[mbase + tid];

    const __nv_bfloat16* Ah_g = g_xh + (size_t)mbase * HDIM;
    const __nv_bfloat16* Al_g = g_xl + (size_t)mbase * HDIM;
    const __nv_bfloat16* Bh_g = g_wh + ((size_t)e * HDIM + n0) * HDIM;
    const __nv_bfloat16* Bl_g = g_wl + ((size_t)e * HDIM + n0) * HDIM;

    // fill one stage for k-step kt: 2048 x 16B chunks over 256 threads
    auto fill = [&](int stage, int kt) {
        uint32_t sbase = st0 + stage * STAGE_B;
        int k0 = kt * 32;
#pragma unroll
        for (int i = 0; i < 8; i++) {
            int cid = tid + i * 256;
            int mat = cid >> 9;
            int win = cid & 511;
            int rr  = win >> 2;
            int cc  = win & 3;
            const __nv_bfloat16* gb =
                (mat == 0) ? Ah_g : (mat == 1) ? Al_g : (mat == 2) ? Bh_g : Bl_g;
            const __nv_bfloat16* gp = gb + (size_t)rr * HDIM + k0 + cc * 8;
            uint32_t sm = sbase + mat * MAT_B + rr * 80 + cc * 16;
            CP_ASYNC16(sm, gp);
        }
    };

    fill(0, 0); CP_COMMIT();
    fill(1, 1); CP_COMMIT();
    fill(2, 2); CP_COMMIT();

    float acc[4][4][4];
#pragma unroll
    for (int a = 0; a < 4; a++)
#pragma unroll
        for (int b = 0; b < 4; b++)
#pragma unroll
            for (int c = 0; c < 4; c++) acc[a][b][c] = 0.f;

    for (int kt = 0; kt < KSTEPS; kt++) {
        CP_WAIT2();
        __syncthreads();
        int nxt = kt + 3;
        if (nxt < KSTEPS) fill(nxt & 3, nxt);
        CP_COMMIT();

        uint32_t sbase = st0 + (kt & 3) * STAGE_B;
        uint32_t sAh = sbase, sBh = sbase + 2 * MAT_B;
#pragma unroll
        for (int k16 = 0; k16 < 2; k16++) {
            uint32_t ah[4][4], al[4][4];
#pragma unroll
            for (int mi = 0; mi < 4; mi++) {
                uint32_t ad = sAh
                    + (uint32_t)((wm * 64 + mi * 16 + (lane & 15)) * 80)
                    + (uint32_t)((k16 * 16 + (lane >> 4) * 8) * 2);
                ldsm_x4(ah[mi], ad);
                ldsm_x4(al[mi], ad + MAT_B);
            }
            uint32_t bh[2][4], bl[2][4];
#pragma unroll
            for (int j = 0; j < 2; j++) {
                uint32_t bd = sBh
                    + (uint32_t)((wn * 32 + j * 16 + (lane & 7) + ((lane >> 4) << 3)) * 80)
                    + (uint32_t)((k16 * 16 + (((lane >> 3) & 1) << 3)) * 2);
                ldsm_x4(bh[j], bd);
                ldsm_x4(bl[j], bd + MAT_B);
            }
#pragma unroll
            for (int mi = 0; mi < 4; mi++)
#pragma unroll
                for (int j = 0; j < 2; j++)
#pragma unroll
                    for (int s = 0; s < 2; s++) {
                        int n8 = j * 2 + s;
                        mma16816(acc[mi][n8], ah[mi], &bh[j][s * 2]);
                        mma16816(acc[mi][n8], ah[mi], &bl[j][s * 2]);
                        mma16816(acc[mi][n8], al[mi], &bh[j][s * 2]);
                    }
        }
    }

    // epilogue: scale rows by combine weight, write to ybuf
#pragma unroll
    for (int mi = 0; mi < 4; mi++) {
        int r = wm * 64 + mi * 16 + (lane >> 2);
        float w0 = s_w[r], w1 = s_w[r + 8];
        size_t b0 = (size_t)(mbase + r) * HDIM + n0;
#pragma unroll
        for (int n8 = 0; n8 < 4; n8++) {
            int c = wn * 32 + n8 * 8 + (lane & 3) * 2;
            float2 v0 = make_float2(acc[mi][n8][0] * w0, acc[mi][n8][1] * w0);
            float2 v1 = make_float2(acc[mi][n8][2] * w1, acc[mi][n8][3] * w1);
            *(float2*)(g_ybuf + b0 + c) = v0;
            *(float2*)(g_ybuf + b0 + (size_t)8 * HDIM + c) = v1;
        }
    }
}

// ============================================================================
// K6: combine — out[t] = ybuf[slot0(t)] + ybuf[slot1(t)] (weights pre-applied)
// ============================================================================
__global__ void moe_combine_kernel(float* __restrict__ out) {
    int i = blockIdx.x * blockDim.x + threadIdx.x;   // float4 index, T*H/4
    int t  = i >> 9;
    int h4 = i & 511;
    int s0 = g_tok_slot[2 * t + 0];
    int s1 = g_tok_slot[2 * t + 1];
    float4 a = *(const float4*)(g_ybuf + (size_t)s0 * HDIM + h4 * 4);
    float4 b = *(const float4*)(g_ybuf + (size_t)s1 * HDIM + h4 * 4);
    float4 o;
    o.x = a.x + b.x; o.y = a.y + b.y; o.z = a.z + b.z; o.w = a.w + b.w;
    ((float4*)out)[i] = o;
}

// ============================================================================
// Launch
// ============================================================================
extern "C" void kernel_launch(void* const* d_in, const int* in_sizes, int n_in,
                              void* d_out, int out_size) {
    const float* x  = (const float*)d_in[0];   // hidden_states [T, H]
    const float* gw = (const float*)d_in[1];   // gate_w [E, H]
    const float* ew = (const float*)d_in[2];   // expert_w [E, H, H]
    float* out    = (float*)d_out;                       // [T, H]
    float* logits = out + (size_t)T_TOK * HDIM;          // [T, E] after out

    cudaFuncSetAttribute(moe_gemm_kernel,
                         cudaFuncAttributeMaxDynamicSharedMemorySize, SMEM_DYN);

    moe_init_kernel<<<1, 256>>>();
    moe_router_kernel<<<(T_TOK * 32) / 256, 256>>>(x, gw, logits);
    moe_scan_kernel<<<1, 32>>>();
    moe_assign_kernel<<<T_TOK / 256, 256>>>();
    moe_convert_x_kernel<<<(NSLOTS * 512) / 256, 256>>>(x);
    moe_convert_w_kernel<<<(NEXP * HDIM * HDIM / 4) / 256, 256>>>(ew);
    moe_gemm_kernel<<<dim3(16, MAX_TILES), 256, SMEM_DYN>>>();
    moe_combine_kernel<<<(T_TOK * (HDIM / 4)) / 256, 256>>>(out);
}

// round 4
// speedup vs baseline: 1.1253x; 1.1253x over previous
#include <cuda_runtime.h>
#include <cuda_bf16.h>
#include <cstdint>

// ============================================================================
// Problem constants
// ============================================================================
#define T_TOK   8192          // B*S tokens
#define HDIM    2048
#define NEXP    8
#define NSLOTS  17408         // 2*T + 8*128 padding
#define MAX_TILES 136         // sum ceil(count_e/128) <= 2T/128 + E
#define KSTEPS  64            // K=2048 / 32 per k-step

// ============================================================================
// PTX helpers — ONLY family-portable (non-"a") instructions:
// mma.sync (sm_80), ldmatrix (sm_75), cp.async (sm_80).
// ============================================================================
__device__ __forceinline__ uint32_t smem_to_u32(const void* p) {
    uint32_t a;
    asm("{ .reg .u64 t; cvta.to.shared.u64 t, %1; cvt.u32.u64 %0, t; }"
        : "=r"(a) : "l"(p));
    return a;
}

#define CP_ASYNC16(smem, gmem) \
    asm volatile("cp.async.cg.shared.global [%0], [%1], 16;" \
        :: "r"(smem), "l"(gmem))
#define CP_COMMIT() asm volatile("cp.async.commit_group;" ::: "memory")
#define CP_WAIT1()  asm volatile("cp.async.wait_group 1;" ::: "memory")

__device__ __forceinline__ void ldsm_x4(uint32_t* r, uint32_t addr) {
    asm volatile("ldmatrix.sync.aligned.m8n8.x4.shared.b16 {%0,%1,%2,%3}, [%4];"
        : "=r"(r[0]), "=r"(r[1]), "=r"(r[2]), "=r"(r[3]) : "r"(addr));
}

__device__ __forceinline__ void mma16816(float* d, const uint32_t* a,
                                         const uint32_t* b) {
    asm volatile(
        "mma.sync.aligned.m16n8k16.row.col.f32.bf16.bf16.f32 "
        "{%0,%1,%2,%3}, {%4,%5,%6,%7}, {%8,%9}, {%0,%1,%2,%3};"
        : "+f"(d[0]), "+f"(d[1]), "+f"(d[2]), "+f"(d[3])
        : "r"(a[0]), "r"(a[1]), "r"(a[2]), "r"(a[3]), "r"(b[0]), "r"(b[1]));
}

// pack (a,b) -> bf16x2 with a in low half (memory order [a, b])
#define CVT_BF16X2_F32(result, a, b) \
    asm("cvt.rn.satfinite.bf16x2.f32 %0, %1, %2;" : "=r"(result) : "f"(b), "f"(a))

// ============================================================================
// Device scratch (no allocations allowed — static __device__ arrays)
// ============================================================================
__device__ int   g_count[NEXP];
__device__ int   g_cursor[NEXP];
__device__ int   g_base[NEXP];
__device__ int   g_tile_expert[MAX_TILES];
__device__ int   g_tile_mbase[MAX_TILES];
__device__ int   g_num_tiles;
__device__ int   g_topi[T_TOK * 2];
__device__ float g_topw[T_TOK * 2];
__device__ int   g_slot_token[NSLOTS];     // zero-init; padding rows are
__device__ float g_slot_w[NSLOTS];         // never read by combine -> no clear
__device__ int   g_tok_slot[T_TOK * 2];

__device__ __nv_bfloat16 g_xh[(size_t)NSLOTS * HDIM];          // 68 MB
__device__ __nv_bfloat16 g_xl[(size_t)NSLOTS * HDIM];          // 68 MB
__device__ __nv_bfloat16 g_wh[(size_t)NEXP * HDIM * HDIM];     // 64 MB
__device__ __nv_bfloat16 g_wl[(size_t)NEXP * HDIM * HDIM];     // 64 MB
__device__ float g_ybuf[(size_t)NSLOTS * HDIM];                // 143 MB

// ============================================================================
// K0: reset counters only (graph replayed; padding slots need no clear)
// ============================================================================
__global__ void moe_init_kernel() {
    int tid = threadIdx.x;
    if (tid < NEXP) { g_count[tid] = 0; g_cursor[tid] = 0; }
}

// ============================================================================
// K1: router — logits (to output tail) + top-2 normalized weights.
// One warp per token.
// ============================================================================
__global__ void moe_router_kernel(const float* __restrict__ x,
                                  const float* __restrict__ gw,
                                  float* __restrict__ logits_out) {
    int warp = (blockIdx.x * blockDim.x + threadIdx.x) >> 5;
    int lane = threadIdx.x & 31;
    if (warp >= T_TOK) return;
    const float4* xr = (const float4*)(x + (size_t)warp * HDIM);
    float acc[NEXP];
#pragma unroll
    for (int e = 0; e < NEXP; e++) acc[e] = 0.f;
    for (int i = lane; i < HDIM / 4; i += 32) {
        float4 xv = xr[i];
#pragma unroll
        for (int e = 0; e < NEXP; e++) {
            float4 gv = ((const float4*)(gw + e * HDIM))[i];
            acc[e] += xv.x * gv.x + xv.y * gv.y + xv.z * gv.z + xv.w * gv.w;
        }
    }
#pragma unroll
    for (int e = 0; e < NEXP; e++)
#pragma unroll
        for (int off = 16; off; off >>= 1)
            acc[e] += __shfl_xor_sync(0xFFFFFFFFu, acc[e], off);
    if (lane == 0) {
#pragma unroll
        for (int e = 0; e < NEXP; e++) logits_out[warp * NEXP + e] = acc[e];
        int i1 = 0; float l1 = acc[0];
#pragma unroll
        for (int e = 1; e < NEXP; e++) if (acc[e] > l1) { l1 = acc[e]; i1 = e; }
        int i2 = -1; float l2 = -3.4e38f;
#pragma unroll
        for (int e = 0; e < NEXP; e++)
            if (e != i1 && acc[e] > l2) { l2 = acc[e]; i2 = e; }
        float ex = expf(l2 - l1);
        float w1 = 1.0f / (1.0f + ex);
        float w2 = ex / (1.0f + ex);
        g_topi[warp * 2 + 0] = i1;  g_topw[warp * 2 + 0] = w1;
        g_topi[warp * 2 + 1] = i2;  g_topw[warp * 2 + 1] = w2;
        atomicAdd(&g_count[i1], 1);
        atomicAdd(&g_count[i2], 1);
    }
}

// ============================================================================
// K2: serial scan — padded slot bases + tile map
// ============================================================================
__global__ void moe_scan_kernel() {
    if (threadIdx.x == 0 && blockIdx.x == 0) {
        int run = 0, nt = 0;
        for (int e = 0; e < NEXP; e++) {
            g_base[e] = run;
            int c = g_count[e];
            int tiles = (c + 127) >> 7;
            for (int t = 0; t < tiles; t++) {
                g_tile_expert[nt] = e;
                g_tile_mbase[nt]  = run + t * 128;
                nt++;
            }
            run += tiles << 7;
        }
        g_num_tiles = nt;
    }
}

// ============================================================================
// K3: scatter tokens into per-expert slot lists.
// Note: padding slots keep stale/zero tokens — their GEMM output rows land in
// ybuf padding rows that combine never reads. Deterministic output regardless.
// ============================================================================
__global__ void moe_assign_kernel() {
    int t = blockIdx.x * blockDim.x + threadIdx.x;
    if (t >= T_TOK) return;
#pragma unroll
    for (int k = 0; k < 2; k++) {
        int e = g_topi[t * 2 + k];
        int pos = atomicAdd(&g_cursor[e], 1);
        int slot = g_base[e] + pos;
        g_slot_token[slot] = t;
        g_slot_w[slot] = g_topw[t * 2 + k];
        g_tok_slot[t * 2 + k] = slot;
    }
}

// ============================================================================
// K4: merged convert — x (slot-gathered) and expert weights -> bf16 hi/lo.
// Merged into ONE launch so the GEMM is launch index 5 (ncu -s 5 -c 1).
// ============================================================================
#define XBLOCKS (NSLOTS * 512 / 256)                 // 34816
#define WBLOCKS (NEXP * HDIM * HDIM / 4 / 256)       // 32768

__global__ void moe_convert_kernel(const float* __restrict__ x,
                                   const float* __restrict__ ew) {
    if (blockIdx.x < XBLOCKS) {
        int i = blockIdx.x * 256 + threadIdx.x;      // NSLOTS*512
        int slot = i >> 9;
        int j = i & 511;                             // float4 within row
        int tok = g_slot_token[slot];
        float4 v = *(const float4*)(x + (size_t)tok * HDIM + j * 4);
        uint32_t h01, h23, l01, l23;
        CVT_BF16X2_F32(h01, v.x, v.y);
        CVT_BF16X2_F32(h23, v.z, v.w);
        float r0 = v.x - __uint_as_float(h01 << 16);
        float r1 = v.y - __uint_as_float(h01 & 0xFFFF0000u);
        float r2 = v.z - __uint_as_float(h23 << 16);
        float r3 = v.w - __uint_as_float(h23 & 0xFFFF0000u);
        CVT_BF16X2_F32(l01, r0, r1);
        CVT_BF16X2_F32(l23, r2, r3);
        size_t o = (size_t)slot * 512 + j;
        ((uint2*)g_xh)[o] = make_uint2(h01, h23);
        ((uint2*)g_xl)[o] = make_uint2(l01, l23);
    } else {
        size_t i = (size_t)(blockIdx.x - XBLOCKS) * 256 + threadIdx.x;
        float4 v = ((const float4*)ew)[i];
        uint32_t h01, h23, l01, l23;
        CVT_BF16X2_F32(h01, v.x, v.y);
        CVT_BF16X2_F32(h23, v.z, v.w);
        float r0 = v.x - __uint_as_float(h01 << 16);
        float r1 = v.y - __uint_as_float(h01 & 0xFFFF0000u);
        float r2 = v.z - __uint_as_float(h23 << 16);
        float r3 = v.w - __uint_as_float(h23 & 0xFFFF0000u);
        CVT_BF16X2_F32(l01, r0, r1);
        CVT_BF16X2_F32(l23, r2, r3);
        ((uint2*)g_wh)[i] = make_uint2(h01, h23);
        ((uint2*)g_wl)[i] = make_uint2(l01, l23);
    }
}

// ============================================================================
// K5: grouped GEMM — 128(M)x128(N)x2048(K), mma.sync bf16 hi/lo (3 terms),
// 2-stage cp.async pipeline, 2 CTAs/SM, term-major MMA ordering (RAW dist 16).
// ============================================================================
#define RS        40                      // padded row length in bf16 elems
#define MAT_B     (128 * RS * 2)          // 10240 B per matrix
#define STAGE_B   (4 * MAT_B)             // 40960 B per stage (Ah,Al,Bh,Bl)
#define NSTAGE    2
#define SMEM_DYN  (1024 + NSTAGE * STAGE_B)   // 82944 B -> 2 CTAs/SM

__global__ void __launch_bounds__(256, 2)
moe_gemm_kernel() {
    int tile = blockIdx.y;
    if (tile >= g_num_tiles) return;
    int n0    = blockIdx.x * 128;
    int e     = g_tile_expert[tile];
    int mbase = g_tile_mbase[tile];

    extern __shared__ char dsm[];
    float* s_w = (float*)dsm;                       // 128 floats
    uint32_t sb = smem_to_u32(dsm);
    uint32_t st0 = sb + 1024;

    int tid = threadIdx.x, lane = tid & 31, wid = tid >> 5;
    int wm = wid >> 2, wn = wid & 3;                // 2 x 4 warp grid

    if (tid < 128) s_w[tid] = g_slot_w[mbase + tid];

    const __nv_bfloat16* Ah_g = g_xh + (size_t)mbase * HDIM;
    const __nv_bfloat16* Al_g = g_xl + (size_t)mbase * HDIM;
    const __nv_bfloat16* Bh_g = g_wh + ((size_t)e * HDIM + n0) * HDIM;
    const __nv_bfloat16* Bl_g = g_wl + ((size_t)e * HDIM + n0) * HDIM;

    // fill one stage for k-step kt: 2048 x 16B chunks over 256 threads
    auto fill = [&](int stage, int kt) {
        uint32_t sbase = st0 + stage * STAGE_B;
        int k0 = kt * 32;
#pragma unroll
        for (int i = 0; i < 8; i++) {
            int cid = tid + i * 256;
            int mat = cid >> 9;
            int win = cid & 511;
            int rr  = win >> 2;
            int cc  = win & 3;
            const __nv_bfloat16* gb =
                (mat == 0) ? Ah_g : (mat == 1) ? Al_g : (mat == 2) ? Bh_g : Bl_g;
            const __nv_bfloat16* gp = gb + (size_t)rr * HDIM + k0 + cc * 8;
            uint32_t sm = sbase + mat * MAT_B + rr * 80 + cc * 16;
            CP_ASYNC16(sm, gp);
        }
    };

    fill(0, 0); CP_COMMIT();
    fill(1, 1); CP_COMMIT();

    float acc[4][4][4];
#pragma unroll
    for (int a = 0; a < 4; a++)
#pragma unroll
        for (int b = 0; b < 4; b++)
#pragma unroll
            for (int c = 0; c < 4; c++) acc[a][b][c] = 0.f;

    for (int kt = 0; kt < KSTEPS; kt++) {
        CP_WAIT1();
        __syncthreads();

        uint32_t sbase = st0 + (kt & 1) * STAGE_B;
        uint32_t sAh = sbase, sBh = sbase + 2 * MAT_B;
#pragma unroll
        for (int k16 = 0; k16 < 2; k16++) {
            uint32_t ah[4][4], al[4][4];
#pragma unroll
            for (int mi = 0; mi < 4; mi++) {
                uint32_t ad = sAh
                    + (uint32_t)((wm * 64 + mi * 16 + (lane & 15)) * 80)
                    + (uint32_t)((k16 * 16 + (lane >> 4) * 8) * 2);
                ldsm_x4(ah[mi], ad);
                ldsm_x4(al[mi], ad + MAT_B);
            }
            uint32_t bh[2][4], bl[2][4];
#pragma unroll
            for (int j = 0; j < 2; j++) {
                uint32_t bd = sBh
                    + (uint32_t)((wn * 32 + j * 16 + (lane & 7) + ((lane >> 4) << 3)) * 80)
                    + (uint32_t)((k16 * 16 + (((lane >> 3) & 1) << 3)) * 2);
                ldsm_x4(bh[j], bd);
                ldsm_x4(bl[j], bd + MAT_B);
            }
            // term-major: same accumulator reused at distance 16 instructions
#pragma unroll
            for (int mi = 0; mi < 4; mi++)
#pragma unroll
                for (int j = 0; j < 2; j++)
#pragma unroll
                    for (int s = 0; s < 2; s++)
                        mma16816(acc[mi][j * 2 + s], ah[mi], &bh[j][s * 2]);
#pragma unroll
            for (int mi = 0; mi < 4; mi++)
#pragma unroll
                for (int j = 0; j < 2; j++)
#pragma unroll
                    for (int s = 0; s < 2; s++)
                        mma16816(acc[mi][j * 2 + s], ah[mi], &bl[j][s * 2]);
#pragma unroll
            for (int mi = 0; mi < 4; mi++)
#pragma unroll
                for (int j = 0; j < 2; j++)
#pragma unroll
                    for (int s = 0; s < 2; s++)
                        mma16816(acc[mi][j * 2 + s], al[mi], &bh[j][s * 2]);
        }

        __syncthreads();
        int nxt = kt + 2;
        if (nxt < KSTEPS) fill(kt & 1, nxt);
        CP_COMMIT();
    }

    // epilogue: scale rows by combine weight, write to ybuf
#pragma unroll
    for (int mi = 0; mi < 4; mi++) {
        int r = wm * 64 + mi * 16 + (lane >> 2);
        float w0 = s_w[r], w1 = s_w[r + 8];
        size_t b0 = (size_t)(mbase + r) * HDIM + n0;
#pragma unroll
        for (int n8 = 0; n8 < 4; n8++) {
            int c = wn * 32 + n8 * 8 + (lane & 3) * 2;
            float2 v0 = make_float2(acc[mi][n8][0] * w0, acc[mi][n8][1] * w0);
            float2 v1 = make_float2(acc[mi][n8][2] * w1, acc[mi][n8][3] * w1);
            *(float2*)(g_ybuf + b0 + c) = v0;
            *(float2*)(g_ybuf + b0 + (size_t)8 * HDIM + c) = v1;
        }
    }
}

// ============================================================================
// K6: combine — out[t] = ybuf[slot0(t)] + ybuf[slot1(t)] (weights pre-applied)
// ============================================================================
__global__ void moe_combine_kernel(float* __restrict__ out) {
    int i = blockIdx.x * blockDim.x + threadIdx.x;   // float4 index, T*H/4
    int t  = i >> 9;
    int h4 = i & 511;
    int s0 = g_tok_slot[2 * t + 0];
    int s1 = g_tok_slot[2 * t + 1];
    float4 a = *(const float4*)(g_ybuf + (size_t)s0 * HDIM + h4 * 4);
    float4 b = *(const float4*)(g_ybuf + (size_t)s1 * HDIM + h4 * 4);
    float4 o;
    o.x = a.x + b.x; o.y = a.y + b.y; o.z = a.z + b.z; o.w = a.w + b.w;
    ((float4*)out)[i] = o;
}

// ============================================================================
// Launch — GEMM is launch index 5 so ncu (-s 5 -c 1) captures it.
// ============================================================================
extern "C" void kernel_launch(void* const* d_in, const int* in_sizes, int n_in,
                              void* d_out, int out_size) {
    const float* x  = (const float*)d_in[0];   // hidden_states [T, H]
    const float* gw = (const float*)d_in[1];   // gate_w [E, H]
    const float* ew = (const float*)d_in[2];   // expert_w [E, H, H]
    float* out    = (float*)d_out;                       // [T, H]
    float* logits = out + (size_t)T_TOK * HDIM;          // [T, E] after out

    cudaFuncSetAttribute(moe_gemm_kernel,
                         cudaFuncAttributeMaxDynamicSharedMemorySize, SMEM_DYN);

    moe_init_kernel<<<1, 32>>>();                                    // 0
    moe_router_kernel<<<(T_TOK * 32) / 256, 256>>>(x, gw, logits);   // 1
    moe_scan_kernel<<<1, 32>>>();                                    // 2
    moe_assign_kernel<<<T_TOK / 256, 256>>>();                       // 3
    moe_convert_kernel<<<XBLOCKS + WBLOCKS, 256>>>(x, ew);           // 4
    moe_gemm_kernel<<<dim3(16, MAX_TILES), 256, SMEM_DYN>>>();       // 5
    moe_combine_kernel<<<(T_TOK * (HDIM / 4)) / 256, 256>>>(out);    // 6
}